// round 8
// baseline (speedup 1.0000x reference)
#include <cuda_runtime.h>
#include <cuda_bf16.h>

#define NN 50000
#define EE 600000
#define DD 128
#define KK 8
#define BB 64
#define ED 16
#define PS 8   // slices per graph for pooling

// Scratch (device globals; no runtime alloc)
__device__ float g_h[NN * DD];            // (1+eps)*x + agg, then relu(h@W1+b1) in-place
__device__ float g_xres[NN * DD];         // MLP output
__device__ float g_psum[BB * KK * DD];    // pocket sums
__device__ float g_pcnt[BB * KK];         // pocket counts
__device__ float g_pemb[BB * KK * DD];    // pocket embeddings
__device__ int   g_gstart[BB + 1];        // graph start offsets (batch sorted)
__device__ float g_part[BB * PS * KK * DD];   // pooling partials (atomic-free)
__device__ float g_cntpart[BB * PS * KK];

// packed-fp32 helpers (FFMA2: exact fp32 math, 2x fma-pipe throughput)
#define FMA2(acc, a2, w2) \
    asm("fma.rn.f32x2 %0, %1, %2, %0;" : "+l"(acc) : "l"(a2), "l"(w2))
#define ADD2(acc, b2) \
    asm("add.rn.f32x2 %0, %0, %1;" : "+l"(acc) : "l"(b2))
#define DUP2(a2, f) \
    asm("mov.b64 %0, {%1, %1};" : "=l"(a2) : "f"(f))
#define PACK2(p, lo, hi) \
    asm("mov.b64 %0, {%1, %2};" : "=l"(p) : "f"(lo), "f"(hi))
#define UNPACK2(lo, hi, p) \
    asm("mov.b64 {%0, %1}, %2;" : "=f"(lo), "=f"(hi) : "l"(p))

// ---------------------------------------------------------------------------
// Kernel 0: g_h = (1+eps)*x
// ---------------------------------------------------------------------------
__global__ void init_kernel(const float* __restrict__ x, const float* __restrict__ epsp) {
    const float c = 1.0f + epsp[0];
    int tid = blockIdx.x * blockDim.x + threadIdx.x;
    int stride = gridDim.x * blockDim.x;
    const float4* x4 = (const float4*)x;
    float4* h4 = (float4*)g_h;
    for (int i = tid; i < NN * DD / 4; i += stride) {
        float4 v = x4[i];
        v.x *= c; v.y *= c; v.z *= c; v.w *= c;
        h4[i] = v;
    }
}

// ---------------------------------------------------------------------------
// Kernel 0b: graph boundary offsets from sorted batch
// ---------------------------------------------------------------------------
__global__ void bounds_kernel(const int* __restrict__ batch) {
    int n = blockIdx.x * blockDim.x + threadIdx.x;
    if (n >= NN) return;
    int b1 = batch[n];
    int b0 = (n == 0) ? -1 : batch[n - 1];
    for (int g = b0 + 1; g <= b1; g++) g_gstart[g] = n;
    if (n == NN - 1)
        for (int g = b1 + 1; g <= BB; g++) g_gstart[g] = NN;
}

// ---------------------------------------------------------------------------
// Kernel 1: edges. Warp per edge; We column-slice held in REGISTERS (64/lane),
// ea via uniform LDG (L1 broadcast). Zero per-edge smem traffic.
// ---------------------------------------------------------------------------
__global__ void __launch_bounds__(256)
edge_kernel(const float* __restrict__ x,
            const int* __restrict__ ei,
            const float* __restrict__ ea,
            const float* __restrict__ We,
            const float* __restrict__ be) {
    const int lane = threadIdx.x & 31;
    const int c0 = lane * 4;

    // Per-lane W slice: We[k][c0..c0+3], k=0..15 -> 32 packed-f32x2 regs
    ulonglong2 w[ED];
#pragma unroll
    for (int k = 0; k < ED; k++)
        w[k] = *(const ulonglong2*)(We + k * DD + c0);
    float4 bbv = *(const float4*)(be + c0);
    unsigned long long b0, b1, z0;
    PACK2(b0, bbv.x, bbv.y);
    PACK2(b1, bbv.z, bbv.w);
    PACK2(z0, 0.f, 0.f);

    const int warp = blockIdx.x * (blockDim.x >> 5) + (threadIdx.x >> 5);
    const int nwarps = gridDim.x * (blockDim.x >> 5);
    const int* __restrict__ srcp = ei;
    const int* __restrict__ dstp = ei + EE;

    for (int e = warp; e < EE; e += nwarps) {
        const float4* eap = (const float4*)(ea + (size_t)e * ED);
        float4 a0 = __ldg(eap + 0);
        float4 a1 = __ldg(eap + 1);
        float4 a2 = __ldg(eap + 2);
        float4 a3 = __ldg(eap + 3);
        int s = __ldg(srcp + e);
        int d = __ldg(dstp + e);

        // 4 independent accumulation chains (p0,p1,q0,q1), length 8 each
        unsigned long long p0 = b0, p1 = b1, q0 = z0, q1 = z0;
        unsigned long long t0, t1, t2, t3;
        DUP2(t0, a0.x); FMA2(p0, t0, w[0].x);  FMA2(p1, t0, w[0].y);
        DUP2(t1, a0.y); FMA2(q0, t1, w[1].x);  FMA2(q1, t1, w[1].y);
        DUP2(t2, a0.z); FMA2(p0, t2, w[2].x);  FMA2(p1, t2, w[2].y);
        DUP2(t3, a0.w); FMA2(q0, t3, w[3].x);  FMA2(q1, t3, w[3].y);
        DUP2(t0, a1.x); FMA2(p0, t0, w[4].x);  FMA2(p1, t0, w[4].y);
        DUP2(t1, a1.y); FMA2(q0, t1, w[5].x);  FMA2(q1, t1, w[5].y);
        DUP2(t2, a1.z); FMA2(p0, t2, w[6].x);  FMA2(p1, t2, w[6].y);
        DUP2(t3, a1.w); FMA2(q0, t3, w[7].x);  FMA2(q1, t3, w[7].y);
        DUP2(t0, a2.x); FMA2(p0, t0, w[8].x);  FMA2(p1, t0, w[8].y);
        DUP2(t1, a2.y); FMA2(q0, t1, w[9].x);  FMA2(q1, t1, w[9].y);
        DUP2(t2, a2.z); FMA2(p0, t2, w[10].x); FMA2(p1, t2, w[10].y);
        DUP2(t3, a2.w); FMA2(q0, t3, w[11].x); FMA2(q1, t3, w[11].y);
        DUP2(t0, a3.x); FMA2(p0, t0, w[12].x); FMA2(p1, t0, w[12].y);
        DUP2(t1, a3.y); FMA2(q0, t1, w[13].x); FMA2(q1, t1, w[13].y);
        DUP2(t2, a3.z); FMA2(p0, t2, w[14].x); FMA2(p1, t2, w[14].y);
        DUP2(t3, a3.w); FMA2(q0, t3, w[15].x); FMA2(q1, t3, w[15].y);
        ADD2(p0, q0);
        ADD2(p1, q1);

        float ex, ey, ez, ew;
        UNPACK2(ex, ey, p0);
        UNPACK2(ez, ew, p1);
        float4 xv = __ldg((const float4*)(x + (size_t)s * DD + c0));
        float mx = fmaxf(ex + xv.x, 0.f);
        float my = fmaxf(ey + xv.y, 0.f);
        float mz = fmaxf(ez + xv.z, 0.f);
        float mw = fmaxf(ew + xv.w, 0.f);
        float* p = g_h + (size_t)d * DD + c0;
        asm volatile("red.global.add.v4.f32 [%0], {%1, %2, %3, %4};"
                     :: "l"(p), "f"(mx), "f"(my), "f"(mz), "f"(mw) : "memory");
    }
}

// ---------------------------------------------------------------------------
// Kernel 2: node MLP split into two GEMM kernels (96KB smem, 2 blocks/SM).
// w-tile double-buffered in registers to hide LDS latency.
// ---------------------------------------------------------------------------
#define TM 64
__device__ __forceinline__ void gemm_tile_f32x2(const float* __restrict__ sW,
                                                const float* __restrict__ sIn,
                                                const float* __restrict__ bias,
                                                int r0, int c0, float4 out[8]) {
    unsigned long long acc[8][2];
    {
        float4 bb = *(const float4*)(bias + c0);
        unsigned long long blo, bhi;
        PACK2(blo, bb.x, bb.y);
        PACK2(bhi, bb.z, bb.w);
#pragma unroll
        for (int i = 0; i < 8; i++) { acc[i][0] = blo; acc[i][1] = bhi; }
    }
    // prefetch first w-chunk
    ulonglong2 wr[4];
#pragma unroll
    for (int q = 0; q < 4; q++)
        wr[q] = *(const ulonglong2*)(sW + q * DD + c0);

#pragma unroll 2
    for (int kk = 0; kk < DD; kk += 4) {
        ulonglong2 wc0 = wr[0], wc1 = wr[1], wc2 = wr[2], wc3 = wr[3];
        const int kn = (kk + 4) & (DD - 1);   // wraps to 0..3 on last iter (harmless)
#pragma unroll
        for (int q = 0; q < 4; q++)
            wr[q] = *(const ulonglong2*)(sW + (kn + q) * DD + c0);
#pragma unroll
        for (int i = 0; i < 8; i++) {
            float4 av = *(const float4*)(sIn + (r0 + i) * DD + kk);
            unsigned long long a2;
            DUP2(a2, av.x); FMA2(acc[i][0], a2, wc0.x); FMA2(acc[i][1], a2, wc0.y);
            DUP2(a2, av.y); FMA2(acc[i][0], a2, wc1.x); FMA2(acc[i][1], a2, wc1.y);
            DUP2(a2, av.z); FMA2(acc[i][0], a2, wc2.x); FMA2(acc[i][1], a2, wc2.y);
            DUP2(a2, av.w); FMA2(acc[i][0], a2, wc3.x); FMA2(acc[i][1], a2, wc3.y);
        }
    }
#pragma unroll
    for (int i = 0; i < 8; i++) {
        float4 v;
        UNPACK2(v.x, v.y, acc[i][0]);
        UNPACK2(v.z, v.w, acc[i][1]);
        out[i] = v;
    }
}

template <bool RELU>
__device__ __forceinline__ void mlp_body(const float* __restrict__ W,
                                         const float* __restrict__ b,
                                         const float* __restrict__ in,
                                         float* __restrict__ outg) {
    extern __shared__ float sm[];
    float* sW = sm;                  // 16384 floats (64KB)
    float* sA = sm + 16384;          // 8192 floats (32KB)
    const int tid = threadIdx.x;

    for (int i = tid; i < 16384 / 4; i += 256)
        ((float4*)sW)[i] = ((const float4*)W)[i];
    const int row0 = blockIdx.x * TM;
    for (int i = tid; i < TM * DD / 4; i += 256) {
        int r = i >> 5;
        int c = i & 31;
        float4 v = make_float4(0.f, 0.f, 0.f, 0.f);
        if (row0 + r < NN) v = ((const float4*)(in + (size_t)(row0 + r) * DD))[c];
        ((float4*)sA)[i] = v;
    }
    __syncthreads();

    const int warp = tid >> 5, lane = tid & 31;
    const int r0 = warp * 8;
    const int c0 = lane * 4;

    float4 res[8];
    gemm_tile_f32x2(sW, sA, b, r0, c0, res);
#pragma unroll
    for (int i = 0; i < 8; i++) {
        int r = row0 + r0 + i;
        if (r < NN) {
            float4 v = res[i];
            if (RELU) {
                v.x = fmaxf(v.x, 0.f); v.y = fmaxf(v.y, 0.f);
                v.z = fmaxf(v.z, 0.f); v.w = fmaxf(v.w, 0.f);
            }
            *(float4*)(outg + (size_t)r * DD + c0) = v;
        }
    }
}

__global__ void __launch_bounds__(256, 2)
mlp1_kernel(const float* __restrict__ W1, const float* __restrict__ b1) {
    mlp_body<true>(W1, b1, g_h, g_h);
}

__global__ void __launch_bounds__(256, 2)
mlp2_kernel(const float* __restrict__ W2, const float* __restrict__ b2) {
    mlp_body<false>(W2, b2, g_h, g_xres);
}

// ---------------------------------------------------------------------------
// Kernel 3: pocket pooling, atomic-free. Block = (graph b, slice s).
// ---------------------------------------------------------------------------
__global__ void pool_kernel(const float* __restrict__ mask) {
    __shared__ float sacc[8][KK * DD];
    __shared__ float scnt[8][KK];
    const int b = blockIdx.x / PS;
    const int s = blockIdx.x % PS;
    const int gs = g_gstart[b];
    const int len = g_gstart[b + 1] - gs;
    const int start = gs + (len * s) / PS;
    const int end = gs + (len * (s + 1)) / PS;

    const int wib = threadIdx.x >> 5;
    const int lane = threadIdx.x & 31;
    float* acc = sacc[wib];
    for (int i = lane; i < KK * DD; i += 32) acc[i] = 0.f;
    float cnt = 0.f;

    for (int n = start + wib; n < end; n += 8) {
        float m = (lane < KK) ? mask[(size_t)n * KK + lane] : 0.f;
        float4 xv = *(const float4*)(g_xres + (size_t)n * DD + lane * 4);
#pragma unroll
        for (int k = 0; k < KK; k++) {
            float mk = __shfl_sync(0xffffffffu, m, k);
            if (mk != 0.f) {
                float4* a = (float4*)(acc + k * DD + lane * 4);
                float4 v = *a;
                v.x += xv.x; v.y += xv.y; v.z += xv.z; v.w += xv.w;
                *a = v;
            }
        }
        cnt += m;
    }
    if (lane < KK) scnt[wib][lane] = cnt;
    __syncthreads();

    float* outp = g_part + (size_t)blockIdx.x * KK * DD;
    for (int i = threadIdx.x; i < KK * DD; i += blockDim.x) {
        float v = 0.f;
#pragma unroll
        for (int w = 0; w < 8; w++) v += sacc[w][i];
        outp[i] = v;
    }
    if (threadIdx.x < KK) {
        float c = 0.f;
#pragma unroll
        for (int w = 0; w < 8; w++) c += scnt[w][threadIdx.x];
        g_cntpart[blockIdx.x * KK + threadIdx.x] = c;
    }
}

// ---------------------------------------------------------------------------
// Kernel 3b: reduce partials -> g_psum, g_pcnt
// ---------------------------------------------------------------------------
__global__ void reduce_kernel() {
    int tid = blockIdx.x * blockDim.x + threadIdx.x;
    int stride = gridDim.x * blockDim.x;
    for (int i = tid; i < BB * KK * DD; i += stride) {
        int b = i / (KK * DD);
        int j = i % (KK * DD);
        float v = 0.f;
#pragma unroll
        for (int s = 0; s < PS; s++) v += g_part[(size_t)(b * PS + s) * KK * DD + j];
        g_psum[i] = v;
    }
    for (int i = tid; i < BB * KK; i += stride) {
        int b = i / KK;
        int k = i % KK;
        float c = 0.f;
#pragma unroll
        for (int s = 0; s < PS; s++) c += g_cntpart[(b * PS + s) * KK + k];
        g_pcnt[i] = c;
    }
}

// ---------------------------------------------------------------------------
// Kernel 4: pocket_emb = (psum/(cnt+1e-9)) @ Wv + bv. Warp per row (512 rows).
// ---------------------------------------------------------------------------
__global__ void pemb_kernel(const float* __restrict__ Wv, const float* __restrict__ bv) {
    const int lane = threadIdx.x & 31;
    const int r = blockIdx.x * (blockDim.x >> 5) + (threadIdx.x >> 5);
    if (r >= BB * KK) return;
    const float rinv = 1.f / (g_pcnt[r] + 1e-9f);
    const int c0 = lane * 4;
    float4 acc = *(const float4*)(bv + c0);
#pragma unroll 8
    for (int d = 0; d < DD; d++) {
        float a = g_psum[r * DD + d] * rinv;
        float4 w = __ldg((const float4*)(Wv + d * DD + c0));
        acc.x += a * w.x; acc.y += a * w.y; acc.z += a * w.z; acc.w += a * w.w;
    }
    *(float4*)(g_pemb + r * DD + c0) = acc;
}

// ---------------------------------------------------------------------------
// Kernel 5: residual pocket feedback + LayerNorm + ReLU. Warp per node.
// ---------------------------------------------------------------------------
__global__ void final_kernel(const float* __restrict__ mask, const int* __restrict__ batch,
                             const float* __restrict__ gamma, const float* __restrict__ beta,
                             float* __restrict__ out) {
    const int lane = threadIdx.x & 31;
    const int gw = blockIdx.x * (blockDim.x >> 5) + (threadIdx.x >> 5);
    const int tw = gridDim.x * (blockDim.x >> 5);
    const int c0 = lane * 4;
    const float4 gm = *(const float4*)(gamma + c0);
    const float4 bt = *(const float4*)(beta + c0);

    for (int n = gw; n < NN; n += tw) {
        int g = batch[n];
        float m = (lane < KK) ? mask[(size_t)n * KK + lane] : 0.f;
        float4 v = *(const float4*)(g_xres + (size_t)n * DD + c0);
        const float* pe = g_pemb + (size_t)g * KK * DD;
#pragma unroll
        for (int k = 0; k < KK; k++) {
            float mk = __shfl_sync(0xffffffffu, m, k);
            if (mk != 0.f) {
                float4 p = __ldg((const float4*)(pe + k * DD + c0));
                v.x += p.x; v.y += p.y; v.z += p.z; v.w += p.w;
            }
        }
        float s = v.x + v.y + v.z + v.w;
#pragma unroll
        for (int off = 16; off; off >>= 1) s += __shfl_xor_sync(0xffffffffu, s, off);
        float mu = s * (1.f / 128.f);
        float dx = v.x - mu, dy = v.y - mu, dz = v.z - mu, dw = v.w - mu;
        float sq = dx * dx + dy * dy + dz * dz + dw * dw;
#pragma unroll
        for (int off = 16; off; off >>= 1) sq += __shfl_xor_sync(0xffffffffu, sq, off);
        float rstd = rsqrtf(sq * (1.f / 128.f) + 1e-5f);
        float4 y;
        y.x = fmaxf(dx * rstd * gm.x + bt.x, 0.f);
        y.y = fmaxf(dy * rstd * gm.y + bt.y, 0.f);
        y.z = fmaxf(dz * rstd * gm.z + bt.z, 0.f);
        y.w = fmaxf(dw * rstd * gm.w + bt.w, 0.f);
        *(float4*)(out + (size_t)n * DD + c0) = y;
    }
}

// ---------------------------------------------------------------------------
extern "C" void kernel_launch(void* const* d_in, const int* in_sizes, int n_in,
                              void* d_out, int out_size) {
    const float* x     = (const float*)d_in[0];
    const int*   ei    = (const int*)d_in[1];
    const float* ea    = (const float*)d_in[2];
    const float* pmask = (const float*)d_in[3];
    const int*   batch = (const int*)d_in[4];
    const float* We    = (const float*)d_in[5];
    const float* be    = (const float*)d_in[6];
    const float* W1    = (const float*)d_in[7];
    const float* b1    = (const float*)d_in[8];
    const float* W2    = (const float*)d_in[9];
    const float* b2    = (const float*)d_in[10];
    const float* eps   = (const float*)d_in[11];
    const float* gamma = (const float*)d_in[12];
    const float* beta  = (const float*)d_in[13];
    const float* Wv    = (const float*)d_in[14];
    const float* bv    = (const float*)d_in[15];
    float* out = (float*)d_out;

    const int MLP_SMEM = (16384 + TM * DD) * 4;   // 98304 bytes
    cudaFuncSetAttribute(mlp1_kernel, cudaFuncAttributeMaxDynamicSharedMemorySize, MLP_SMEM);
    cudaFuncSetAttribute(mlp2_kernel, cudaFuncAttributeMaxDynamicSharedMemorySize, MLP_SMEM);

    init_kernel<<<2048, 256>>>(x, eps);
    bounds_kernel<<<(NN + 255) / 256, 256>>>(batch);
    edge_kernel<<<4096, 256>>>(x, ei, ea, We, be);
    mlp1_kernel<<<(NN + TM - 1) / TM, 256, MLP_SMEM>>>(W1, b1);
    mlp2_kernel<<<(NN + TM - 1) / TM, 256, MLP_SMEM>>>(W2, b2);
    pool_kernel<<<BB * PS, 256>>>(pmask);
    reduce_kernel<<<64, 256>>>();
    pemb_kernel<<<(BB * KK + 7) / 8, 256>>>(Wv, bv);
    final_kernel<<<2048, 256>>>(pmask, batch, gamma, beta, out);
}

// round 9
// speedup vs baseline: 1.6578x; 1.6578x over previous
#include <cuda_runtime.h>
#include <cuda_bf16.h>

#define NN 50000
#define EE 600000
#define DD 128
#define KK 8
#define BB 64
#define ED 16
#define PS 8   // slices per graph for pooling

// Scratch (device globals; no runtime alloc)
__device__ float g_h[NN * DD];            // (1+eps)*x + agg, then relu(h@W1+b1) in-place
__device__ float g_xres[NN * DD];         // MLP output
__device__ float g_psum[BB * KK * DD];    // pocket sums
__device__ float g_pcnt[BB * KK];         // pocket counts
__device__ float g_pemb[BB * KK * DD];    // pocket embeddings
__device__ int   g_gstart[BB + 1];        // graph start offsets (batch sorted)
__device__ float g_part[BB * PS * KK * DD];   // pooling partials (atomic-free)
__device__ float g_cntpart[BB * PS * KK];

// packed-fp32 helpers (FFMA2: exact fp32 math, 2x fma-pipe throughput)
#define FMA2(acc, a2, w2) \
    asm("fma.rn.f32x2 %0, %1, %2, %0;" : "+l"(acc) : "l"(a2), "l"(w2))
#define DUP2(a2, f) \
    asm("mov.b64 %0, {%1, %1};" : "=l"(a2) : "f"(f))
#define PACK2(p, lo, hi) \
    asm("mov.b64 %0, {%1, %2};" : "=l"(p) : "f"(lo), "f"(hi))
#define UNPACK2(lo, hi, p) \
    asm("mov.b64 {%0, %1}, %2;" : "=f"(lo), "=f"(hi) : "l"(p))

// ---------------------------------------------------------------------------
// Kernel 0: g_h = (1+eps)*x
// ---------------------------------------------------------------------------
__global__ void init_kernel(const float* __restrict__ x, const float* __restrict__ epsp) {
    const float c = 1.0f + epsp[0];
    int tid = blockIdx.x * blockDim.x + threadIdx.x;
    int stride = gridDim.x * blockDim.x;
    const float4* x4 = (const float4*)x;
    float4* h4 = (float4*)g_h;
    for (int i = tid; i < NN * DD / 4; i += stride) {
        float4 v = x4[i];
        v.x *= c; v.y *= c; v.z *= c; v.w *= c;
        h4[i] = v;
    }
}

// ---------------------------------------------------------------------------
// Kernel 0b: graph boundary offsets from sorted batch
// ---------------------------------------------------------------------------
__global__ void bounds_kernel(const int* __restrict__ batch) {
    int n = blockIdx.x * blockDim.x + threadIdx.x;
    if (n >= NN) return;
    int b1 = batch[n];
    int b0 = (n == 0) ? -1 : batch[n - 1];
    for (int g = b0 + 1; g <= b1; g++) g_gstart[g] = n;
    if (n == NN - 1)
        for (int g = b1 + 1; g <= BB; g++) g_gstart[g] = NN;
}

// ---------------------------------------------------------------------------
// Kernel 1: edges. Warp processes 4 edges per iteration: sWe row loaded ONCE
// per j per 4 edges (4x less smem crossbar traffic than 1 edge/iter).
// ea staged coalesced (2 floats/lane), broadcast via shfl.
// ---------------------------------------------------------------------------
__global__ void __launch_bounds__(256)
edge_kernel(const float* __restrict__ x,
            const int* __restrict__ ei,
            const float* __restrict__ ea,
            const float* __restrict__ We,
            const float* __restrict__ be) {
    __shared__ float sWe[ED * DD];
    __shared__ float sbe[DD];
    for (int i = threadIdx.x; i < ED * DD / 4; i += blockDim.x)
        ((float4*)sWe)[i] = ((const float4*)We)[i];
    if (threadIdx.x < DD) sbe[threadIdx.x] = be[threadIdx.x];
    __syncthreads();

    const int lane = threadIdx.x & 31;
    const int warp = blockIdx.x * (blockDim.x >> 5) + (threadIdx.x >> 5);
    const int nwarps = gridDim.x * (blockDim.x >> 5);
    const int* __restrict__ srcp = ei;
    const int* __restrict__ dstp = ei + EE;
    const int c0 = lane * 4;

    float4 bbv = *(const float4*)(&sbe[c0]);
    unsigned long long bp0, bp1;
    PACK2(bp0, bbv.x, bbv.y);
    PACK2(bp1, bbv.z, bbv.w);

    const int NG = EE / 4;   // 150000 groups of 4 edges
    for (int g = warp; g < NG; g += nwarps) {
        const int e0 = g * 4;
        // stage 4 edges' attrs: 64 floats, 2 per lane, coalesced
        const float* eab = ea + (size_t)e0 * ED;
        float r0 = __ldg(eab + lane);
        float r1 = __ldg(eab + lane + 32);
        int s0 = __ldg(srcp + e0 + 0), s1 = __ldg(srcp + e0 + 1);
        int s2 = __ldg(srcp + e0 + 2), s3 = __ldg(srcp + e0 + 3);
        int d0 = __ldg(dstp + e0 + 0), d1 = __ldg(dstp + e0 + 1);
        int d2 = __ldg(dstp + e0 + 2), d3 = __ldg(dstp + e0 + 3);

        unsigned long long acc[4][2];
#pragma unroll
        for (int i = 0; i < 4; i++) { acc[i][0] = bp0; acc[i][1] = bp1; }

#pragma unroll
        for (int j = 0; j < ED; j++) {
            ulonglong2 w = *(const ulonglong2*)(&sWe[j * DD + c0]);
            float a0 = __shfl_sync(0xffffffffu, r0, j);
            float a1 = __shfl_sync(0xffffffffu, r0, 16 + j);
            float a2 = __shfl_sync(0xffffffffu, r1, j);
            float a3 = __shfl_sync(0xffffffffu, r1, 16 + j);
            unsigned long long t0, t1, t2, t3;
            DUP2(t0, a0); FMA2(acc[0][0], t0, w.x); FMA2(acc[0][1], t0, w.y);
            DUP2(t1, a1); FMA2(acc[1][0], t1, w.x); FMA2(acc[1][1], t1, w.y);
            DUP2(t2, a2); FMA2(acc[2][0], t2, w.x); FMA2(acc[2][1], t2, w.y);
            DUP2(t3, a3); FMA2(acc[3][0], t3, w.x); FMA2(acc[3][1], t3, w.y);
        }

        const int sidx[4] = {s0, s1, s2, s3};
        const int didx[4] = {d0, d1, d2, d3};
#pragma unroll
        for (int i = 0; i < 4; i++) {
            float ex, ey, ez, ew;
            UNPACK2(ex, ey, acc[i][0]);
            UNPACK2(ez, ew, acc[i][1]);
            float4 xv = __ldg((const float4*)(x + (size_t)sidx[i] * DD + c0));
            float mx = fmaxf(ex + xv.x, 0.f);
            float my = fmaxf(ey + xv.y, 0.f);
            float mz = fmaxf(ez + xv.z, 0.f);
            float mw = fmaxf(ew + xv.w, 0.f);
            float* p = g_h + (size_t)didx[i] * DD + c0;
            asm volatile("red.global.add.v4.f32 [%0], {%1, %2, %3, %4};"
                         :: "l"(p), "f"(mx), "f"(my), "f"(mz), "f"(mw) : "memory");
        }
    }
}

// ---------------------------------------------------------------------------
// Kernel 2: node MLP split into two GEMM kernels (96KB smem, 2 blocks/SM).
// ---------------------------------------------------------------------------
#define TM 64
__device__ __forceinline__ void gemm_tile_f32x2(const float* __restrict__ sW,
                                                const float* __restrict__ sIn,
                                                const float* __restrict__ bias,
                                                int r0, int c0, float4 out[8]) {
    unsigned long long acc[8][2];
    {
        float4 bb = *(const float4*)(bias + c0);
        unsigned long long blo, bhi;
        PACK2(blo, bb.x, bb.y);
        PACK2(bhi, bb.z, bb.w);
#pragma unroll
        for (int i = 0; i < 8; i++) { acc[i][0] = blo; acc[i][1] = bhi; }
    }
    // prefetch first w-chunk
    ulonglong2 wr[4];
#pragma unroll
    for (int q = 0; q < 4; q++)
        wr[q] = *(const ulonglong2*)(sW + q * DD + c0);

#pragma unroll 2
    for (int kk = 0; kk < DD; kk += 4) {
        ulonglong2 wc0 = wr[0], wc1 = wr[1], wc2 = wr[2], wc3 = wr[3];
        const int kn = (kk + 4) & (DD - 1);   // wraps to 0..3 on last iter (harmless)
#pragma unroll
        for (int q = 0; q < 4; q++)
            wr[q] = *(const ulonglong2*)(sW + (kn + q) * DD + c0);
#pragma unroll
        for (int i = 0; i < 8; i++) {
            float4 av = *(const float4*)(sIn + (r0 + i) * DD + kk);
            unsigned long long a2;
            DUP2(a2, av.x); FMA2(acc[i][0], a2, wc0.x); FMA2(acc[i][1], a2, wc0.y);
            DUP2(a2, av.y); FMA2(acc[i][0], a2, wc1.x); FMA2(acc[i][1], a2, wc1.y);
            DUP2(a2, av.z); FMA2(acc[i][0], a2, wc2.x); FMA2(acc[i][1], a2, wc2.y);
            DUP2(a2, av.w); FMA2(acc[i][0], a2, wc3.x); FMA2(acc[i][1], a2, wc3.y);
        }
    }
#pragma unroll
    for (int i = 0; i < 8; i++) {
        float4 v;
        UNPACK2(v.x, v.y, acc[i][0]);
        UNPACK2(v.z, v.w, acc[i][1]);
        out[i] = v;
    }
}

template <bool RELU>
__device__ __forceinline__ void mlp_body(const float* __restrict__ W,
                                         const float* __restrict__ b,
                                         const float* __restrict__ in,
                                         float* __restrict__ outg) {
    extern __shared__ float sm[];
    float* sW = sm;                  // 16384 floats (64KB)
    float* sA = sm + 16384;          // 8192 floats (32KB)
    const int tid = threadIdx.x;

    for (int i = tid; i < 16384 / 4; i += 256)
        ((float4*)sW)[i] = ((const float4*)W)[i];
    const int row0 = blockIdx.x * TM;
    for (int i = tid; i < TM * DD / 4; i += 256) {
        int r = i >> 5;
        int c = i & 31;
        float4 v = make_float4(0.f, 0.f, 0.f, 0.f);
        if (row0 + r < NN) v = ((const float4*)(in + (size_t)(row0 + r) * DD))[c];
        ((float4*)sA)[i] = v;
    }
    __syncthreads();

    const int warp = tid >> 5, lane = tid & 31;
    const int r0 = warp * 8;
    const int c0 = lane * 4;

    float4 res[8];
    gemm_tile_f32x2(sW, sA, b, r0, c0, res);
#pragma unroll
    for (int i = 0; i < 8; i++) {
        int r = row0 + r0 + i;
        if (r < NN) {
            float4 v = res[i];
            if (RELU) {
                v.x = fmaxf(v.x, 0.f); v.y = fmaxf(v.y, 0.f);
                v.z = fmaxf(v.z, 0.f); v.w = fmaxf(v.w, 0.f);
            }
            *(float4*)(outg + (size_t)r * DD + c0) = v;
        }
    }
}

__global__ void __launch_bounds__(256, 2)
mlp1_kernel(const float* __restrict__ W1, const float* __restrict__ b1) {
    mlp_body<true>(W1, b1, g_h, g_h);
}

__global__ void __launch_bounds__(256, 2)
mlp2_kernel(const float* __restrict__ W2, const float* __restrict__ b2) {
    mlp_body<false>(W2, b2, g_h, g_xres);
}

// ---------------------------------------------------------------------------
// Kernel 3: pocket pooling, atomic-free. Block = (graph b, slice s).
// ---------------------------------------------------------------------------
__global__ void pool_kernel(const float* __restrict__ mask) {
    __shared__ float sacc[8][KK * DD];
    __shared__ float scnt[8][KK];
    const int b = blockIdx.x / PS;
    const int s = blockIdx.x % PS;
    const int gs = g_gstart[b];
    const int len = g_gstart[b + 1] - gs;
    const int start = gs + (len * s) / PS;
    const int end = gs + (len * (s + 1)) / PS;

    const int wib = threadIdx.x >> 5;
    const int lane = threadIdx.x & 31;
    float* acc = sacc[wib];
    for (int i = lane; i < KK * DD; i += 32) acc[i] = 0.f;
    float cnt = 0.f;

    for (int n = start + wib; n < end; n += 8) {
        float m = (lane < KK) ? mask[(size_t)n * KK + lane] : 0.f;
        float4 xv = *(const float4*)(g_xres + (size_t)n * DD + lane * 4);
#pragma unroll
        for (int k = 0; k < KK; k++) {
            float mk = __shfl_sync(0xffffffffu, m, k);
            if (mk != 0.f) {
                float4* a = (float4*)(acc + k * DD + lane * 4);
                float4 v = *a;
                v.x += xv.x; v.y += xv.y; v.z += xv.z; v.w += xv.w;
                *a = v;
            }
        }
        cnt += m;
    }
    if (lane < KK) scnt[wib][lane] = cnt;
    __syncthreads();

    float* outp = g_part + (size_t)blockIdx.x * KK * DD;
    for (int i = threadIdx.x; i < KK * DD; i += blockDim.x) {
        float v = 0.f;
#pragma unroll
        for (int w = 0; w < 8; w++) v += sacc[w][i];
        outp[i] = v;
    }
    if (threadIdx.x < KK) {
        float c = 0.f;
#pragma unroll
        for (int w = 0; w < 8; w++) c += scnt[w][threadIdx.x];
        g_cntpart[blockIdx.x * KK + threadIdx.x] = c;
    }
}

// ---------------------------------------------------------------------------
// Kernel 3b: reduce partials -> g_psum, g_pcnt
// ---------------------------------------------------------------------------
__global__ void reduce_kernel() {
    int tid = blockIdx.x * blockDim.x + threadIdx.x;
    int stride = gridDim.x * blockDim.x;
    for (int i = tid; i < BB * KK * DD; i += stride) {
        int b = i / (KK * DD);
        int j = i % (KK * DD);
        float v = 0.f;
#pragma unroll
        for (int s = 0; s < PS; s++) v += g_part[(size_t)(b * PS + s) * KK * DD + j];
        g_psum[i] = v;
    }
    for (int i = tid; i < BB * KK; i += stride) {
        int b = i / KK;
        int k = i % KK;
        float c = 0.f;
#pragma unroll
        for (int s = 0; s < PS; s++) c += g_cntpart[(b * PS + s) * KK + k];
        g_pcnt[i] = c;
    }
}

// ---------------------------------------------------------------------------
// Kernel 4: pocket_emb = (psum/(cnt+1e-9)) @ Wv + bv. Warp per row (512 rows).
// ---------------------------------------------------------------------------
__global__ void pemb_kernel(const float* __restrict__ Wv, const float* __restrict__ bv) {
    const int lane = threadIdx.x & 31;
    const int r = blockIdx.x * (blockDim.x >> 5) + (threadIdx.x >> 5);
    if (r >= BB * KK) return;
    const float rinv = 1.f / (g_pcnt[r] + 1e-9f);
    const int c0 = lane * 4;
    float4 acc = *(const float4*)(bv + c0);
#pragma unroll 8
    for (int d = 0; d < DD; d++) {
        float a = g_psum[r * DD + d] * rinv;
        float4 w = __ldg((const float4*)(Wv + d * DD + c0));
        acc.x += a * w.x; acc.y += a * w.y; acc.z += a * w.z; acc.w += a * w.w;
    }
    *(float4*)(g_pemb + r * DD + c0) = acc;
}

// ---------------------------------------------------------------------------
// Kernel 5: residual pocket feedback + LayerNorm + ReLU. Warp per node.
// ---------------------------------------------------------------------------
__global__ void final_kernel(const float* __restrict__ mask, const int* __restrict__ batch,
                             const float* __restrict__ gamma, const float* __restrict__ beta,
                             float* __restrict__ out) {
    const int lane = threadIdx.x & 31;
    const int gw = blockIdx.x * (blockDim.x >> 5) + (threadIdx.x >> 5);
    const int tw = gridDim.x * (blockDim.x >> 5);
    const int c0 = lane * 4;
    const float4 gm = *(const float4*)(gamma + c0);
    const float4 bt = *(const float4*)(beta + c0);

    for (int n = gw; n < NN; n += tw) {
        int g = batch[n];
        float m = (lane < KK) ? mask[(size_t)n * KK + lane] : 0.f;
        float4 v = *(const float4*)(g_xres + (size_t)n * DD + c0);
        const float* pe = g_pemb + (size_t)g * KK * DD;
#pragma unroll
        for (int k = 0; k < KK; k++) {
            float mk = __shfl_sync(0xffffffffu, m, k);
            if (mk != 0.f) {
                float4 p = __ldg((const float4*)(pe + k * DD + c0));
                v.x += p.x; v.y += p.y; v.z += p.z; v.w += p.w;
            }
        }
        float s = v.x + v.y + v.z + v.w;
#pragma unroll
        for (int off = 16; off; off >>= 1) s += __shfl_xor_sync(0xffffffffu, s, off);
        float mu = s * (1.f / 128.f);
        float dx = v.x - mu, dy = v.y - mu, dz = v.z - mu, dw = v.w - mu;
        float sq = dx * dx + dy * dy + dz * dz + dw * dw;
#pragma unroll
        for (int off = 16; off; off >>= 1) sq += __shfl_xor_sync(0xffffffffu, sq, off);
        float rstd = rsqrtf(sq * (1.f / 128.f) + 1e-5f);
        float4 y;
        y.x = fmaxf(dx * rstd * gm.x + bt.x, 0.f);
        y.y = fmaxf(dy * rstd * gm.y + bt.y, 0.f);
        y.z = fmaxf(dz * rstd * gm.z + bt.z, 0.f);
        y.w = fmaxf(dw * rstd * gm.w + bt.w, 0.f);
        *(float4*)(out + (size_t)n * DD + c0) = y;
    }
}

// ---------------------------------------------------------------------------
extern "C" void kernel_launch(void* const* d_in, const int* in_sizes, int n_in,
                              void* d_out, int out_size) {
    const float* x     = (const float*)d_in[0];
    const int*   ei    = (const int*)d_in[1];
    const float* ea    = (const float*)d_in[2];
    const float* pmask = (const float*)d_in[3];
    const int*   batch = (const int*)d_in[4];
    const float* We    = (const float*)d_in[5];
    const float* be    = (const float*)d_in[6];
    const float* W1    = (const float*)d_in[7];
    const float* b1    = (const float*)d_in[8];
    const float* W2    = (const float*)d_in[9];
    const float* b2    = (const float*)d_in[10];
    const float* eps   = (const float*)d_in[11];
    const float* gamma = (const float*)d_in[12];
    const float* beta  = (const float*)d_in[13];
    const float* Wv    = (const float*)d_in[14];
    const float* bv    = (const float*)d_in[15];
    float* out = (float*)d_out;

    const int MLP_SMEM = (16384 + TM * DD) * 4;   // 98304 bytes
    cudaFuncSetAttribute(mlp1_kernel, cudaFuncAttributeMaxDynamicSharedMemorySize, MLP_SMEM);
    cudaFuncSetAttribute(mlp2_kernel, cudaFuncAttributeMaxDynamicSharedMemorySize, MLP_SMEM);

    init_kernel<<<2048, 256>>>(x, eps);
    bounds_kernel<<<(NN + 255) / 256, 256>>>(batch);
    edge_kernel<<<4096, 256>>>(x, ei, ea, We, be);
    mlp1_kernel<<<(NN + TM - 1) / TM, 256, MLP_SMEM>>>(W1, b1);
    mlp2_kernel<<<(NN + TM - 1) / TM, 256, MLP_SMEM>>>(W2, b2);
    pool_kernel<<<BB * PS, 256>>>(pmask);
    reduce_kernel<<<64, 256>>>();
    pemb_kernel<<<(BB * KK + 7) / 8, 256>>>(Wv, bv);
    final_kernel<<<2048, 256>>>(pmask, batch, gamma, beta, out);
}

// round 10
// speedup vs baseline: 1.6830x; 1.0152x over previous
#include <cuda_runtime.h>
#include <cuda_bf16.h>

#define NN 50000
#define EE 600000
#define DD 128
#define KK 8
#define BB 64
#define ED 16
#define PS 8   // slices per graph for pooling

// Scratch (device globals; no runtime alloc)
__device__ float g_h[NN * DD];            // (1+eps)*x + agg, then relu(h@W1+b1) in-place
__device__ float g_xres[NN * DD];         // MLP output
__device__ float g_psum[BB * KK * DD];    // pocket sums
__device__ float g_pcnt[BB * KK];         // pocket counts
__device__ float g_pemb[BB * KK * DD];    // pocket embeddings
__device__ int   g_gstart[BB + 1];        // graph start offsets (batch sorted)
__device__ float g_part[BB * PS * KK * DD];   // pooling partials (atomic-free)
__device__ float g_cntpart[BB * PS * KK];

// packed-fp32 helpers (FFMA2: exact fp32 math, 2x fma-pipe throughput)
#define FMA2(acc, a2, w2) \
    asm("fma.rn.f32x2 %0, %1, %2, %0;" : "+l"(acc) : "l"(a2), "l"(w2))
#define DUP2(a2, f) \
    asm("mov.b64 %0, {%1, %1};" : "=l"(a2) : "f"(f))
#define PACK2(p, lo, hi) \
    asm("mov.b64 %0, {%1, %2};" : "=l"(p) : "f"(lo), "f"(hi))
#define UNPACK2(lo, hi, p) \
    asm("mov.b64 {%0, %1}, %2;" : "=f"(lo), "=f"(hi) : "l"(p))

// ---------------------------------------------------------------------------
// Kernel 0: g_h = (1+eps)*x
// ---------------------------------------------------------------------------
__global__ void init_kernel(const float* __restrict__ x, const float* __restrict__ epsp) {
    const float c = 1.0f + epsp[0];
    int tid = blockIdx.x * blockDim.x + threadIdx.x;
    int stride = gridDim.x * blockDim.x;
    const float4* x4 = (const float4*)x;
    float4* h4 = (float4*)g_h;
    for (int i = tid; i < NN * DD / 4; i += stride) {
        float4 v = x4[i];
        v.x *= c; v.y *= c; v.z *= c; v.w *= c;
        h4[i] = v;
    }
}

// ---------------------------------------------------------------------------
// Kernel 0b: graph boundary offsets from sorted batch
// ---------------------------------------------------------------------------
__global__ void bounds_kernel(const int* __restrict__ batch) {
    int n = blockIdx.x * blockDim.x + threadIdx.x;
    if (n >= NN) return;
    int b1 = batch[n];
    int b0 = (n == 0) ? -1 : batch[n - 1];
    for (int g = b0 + 1; g <= b1; g++) g_gstart[g] = n;
    if (n == NN - 1)
        for (int g = b1 + 1; g <= BB; g++) g_gstart[g] = NN;
}

// ---------------------------------------------------------------------------
// Kernel 1: edges. Warp processes 4 edges per iteration: sWe row loaded ONCE
// per j per 4 edges (4x less smem crossbar traffic than 1 edge/iter).
// ea staged coalesced (2 floats/lane), broadcast via shfl.
// ---------------------------------------------------------------------------
__global__ void __launch_bounds__(256)
edge_kernel(const float* __restrict__ x,
            const int* __restrict__ ei,
            const float* __restrict__ ea,
            const float* __restrict__ We,
            const float* __restrict__ be) {
    __shared__ float sWe[ED * DD];
    __shared__ float sbe[DD];
    for (int i = threadIdx.x; i < ED * DD / 4; i += blockDim.x)
        ((float4*)sWe)[i] = ((const float4*)We)[i];
    if (threadIdx.x < DD) sbe[threadIdx.x] = be[threadIdx.x];
    __syncthreads();

    const int lane = threadIdx.x & 31;
    const int warp = blockIdx.x * (blockDim.x >> 5) + (threadIdx.x >> 5);
    const int nwarps = gridDim.x * (blockDim.x >> 5);
    const int* __restrict__ srcp = ei;
    const int* __restrict__ dstp = ei + EE;
    const int c0 = lane * 4;

    float4 bbv = *(const float4*)(&sbe[c0]);
    unsigned long long bp0, bp1;
    PACK2(bp0, bbv.x, bbv.y);
    PACK2(bp1, bbv.z, bbv.w);

    const int NG = EE / 4;   // 150000 groups of 4 edges
    for (int g = warp; g < NG; g += nwarps) {
        const int e0 = g * 4;
        // stage 4 edges' attrs: 64 floats, 2 per lane, coalesced
        const float* eab = ea + (size_t)e0 * ED;
        float r0 = __ldg(eab + lane);
        float r1 = __ldg(eab + lane + 32);
        int s0 = __ldg(srcp + e0 + 0), s1 = __ldg(srcp + e0 + 1);
        int s2 = __ldg(srcp + e0 + 2), s3 = __ldg(srcp + e0 + 3);
        int d0 = __ldg(dstp + e0 + 0), d1 = __ldg(dstp + e0 + 1);
        int d2 = __ldg(dstp + e0 + 2), d3 = __ldg(dstp + e0 + 3);

        unsigned long long acc[4][2];
#pragma unroll
        for (int i = 0; i < 4; i++) { acc[i][0] = bp0; acc[i][1] = bp1; }

#pragma unroll
        for (int j = 0; j < ED; j++) {
            ulonglong2 w = *(const ulonglong2*)(&sWe[j * DD + c0]);
            float a0 = __shfl_sync(0xffffffffu, r0, j);
            float a1 = __shfl_sync(0xffffffffu, r0, 16 + j);
            float a2 = __shfl_sync(0xffffffffu, r1, j);
            float a3 = __shfl_sync(0xffffffffu, r1, 16 + j);
            unsigned long long t0, t1, t2, t3;
            DUP2(t0, a0); FMA2(acc[0][0], t0, w.x); FMA2(acc[0][1], t0, w.y);
            DUP2(t1, a1); FMA2(acc[1][0], t1, w.x); FMA2(acc[1][1], t1, w.y);
            DUP2(t2, a2); FMA2(acc[2][0], t2, w.x); FMA2(acc[2][1], t2, w.y);
            DUP2(t3, a3); FMA2(acc[3][0], t3, w.x); FMA2(acc[3][1], t3, w.y);
        }

        const int sidx[4] = {s0, s1, s2, s3};
        const int didx[4] = {d0, d1, d2, d3};
#pragma unroll
        for (int i = 0; i < 4; i++) {
            float ex, ey, ez, ew;
            UNPACK2(ex, ey, acc[i][0]);
            UNPACK2(ez, ew, acc[i][1]);
            float4 xv = __ldg((const float4*)(x + (size_t)sidx[i] * DD + c0));
            float mx = fmaxf(ex + xv.x, 0.f);
            float my = fmaxf(ey + xv.y, 0.f);
            float mz = fmaxf(ez + xv.z, 0.f);
            float mw = fmaxf(ew + xv.w, 0.f);
            float* p = g_h + (size_t)didx[i] * DD + c0;
            asm volatile("red.global.add.v4.f32 [%0], {%1, %2, %3, %4};"
                         :: "l"(p), "f"(mx), "f"(my), "f"(mz), "f"(mw) : "memory");
        }
    }
}

// ---------------------------------------------------------------------------
// Kernel 2: node MLP, two GEMM kernels. W staged through a 16KB quarter
// buffer (4 stages x 32 k-rows) so smem = 48KB and regs <= 64:
// 4 blocks/SM, 32 warps resident (occupancy was the R8/R9 limiter).
// ---------------------------------------------------------------------------
#define TM 64
template <bool RELU>
__device__ __forceinline__ void mlp_body(const float* __restrict__ W,
                                         const float* __restrict__ b,
                                         const float* __restrict__ in,
                                         float* __restrict__ outg) {
    extern __shared__ float sm[];
    float* sWq = sm;                 // 4096 floats (16KB): 32 k-rows x 128 cols
    float* sA  = sm + 4096;          // 8192 floats (32KB): 64 rows x 128
    const int tid = threadIdx.x;
    const int row0 = blockIdx.x * TM;

    for (int i = tid; i < TM * DD / 4; i += 256) {
        int r = i >> 5;
        int c = i & 31;
        float4 v = make_float4(0.f, 0.f, 0.f, 0.f);
        if (row0 + r < NN) v = ((const float4*)(in + (size_t)(row0 + r) * DD))[c];
        ((float4*)sA)[i] = v;
    }

    const int warp = tid >> 5, lane = tid & 31;
    const int r0 = warp * 8;
    const int c0 = lane * 4;

    unsigned long long acc[8][2];
    {
        float4 bb = *(const float4*)(b + c0);
        unsigned long long blo, bhi;
        PACK2(blo, bb.x, bb.y);
        PACK2(bhi, bb.z, bb.w);
#pragma unroll
        for (int i = 0; i < 8; i++) { acc[i][0] = blo; acc[i][1] = bhi; }
    }

#pragma unroll 1
    for (int q = 0; q < 4; q++) {
        __syncthreads();   // q=0: sA ready; q>0: previous stage's compute done
        for (int i = tid; i < 32 * DD / 4; i += 256)
            ((float4*)sWq)[i] = ((const float4*)(W + q * 32 * DD))[i];
        __syncthreads();

        const float* sAq = sA + q * 32;
#pragma unroll 2
        for (int kk = 0; kk < 32; kk += 4) {
            ulonglong2 wc0 = *(const ulonglong2*)(sWq + (kk + 0) * DD + c0);
            ulonglong2 wc1 = *(const ulonglong2*)(sWq + (kk + 1) * DD + c0);
            ulonglong2 wc2 = *(const ulonglong2*)(sWq + (kk + 2) * DD + c0);
            ulonglong2 wc3 = *(const ulonglong2*)(sWq + (kk + 3) * DD + c0);
#pragma unroll
            for (int i = 0; i < 8; i++) {
                float4 av = *(const float4*)(sAq + (r0 + i) * DD + kk);
                unsigned long long a2;
                DUP2(a2, av.x); FMA2(acc[i][0], a2, wc0.x); FMA2(acc[i][1], a2, wc0.y);
                DUP2(a2, av.y); FMA2(acc[i][0], a2, wc1.x); FMA2(acc[i][1], a2, wc1.y);
                DUP2(a2, av.z); FMA2(acc[i][0], a2, wc2.x); FMA2(acc[i][1], a2, wc2.y);
                DUP2(a2, av.w); FMA2(acc[i][0], a2, wc3.x); FMA2(acc[i][1], a2, wc3.y);
            }
        }
    }

#pragma unroll
    for (int i = 0; i < 8; i++) {
        int r = row0 + r0 + i;
        if (r < NN) {
            float4 v;
            UNPACK2(v.x, v.y, acc[i][0]);
            UNPACK2(v.z, v.w, acc[i][1]);
            if (RELU) {
                v.x = fmaxf(v.x, 0.f); v.y = fmaxf(v.y, 0.f);
                v.z = fmaxf(v.z, 0.f); v.w = fmaxf(v.w, 0.f);
            }
            *(float4*)(outg + (size_t)r * DD + c0) = v;
        }
    }
}

__global__ void __launch_bounds__(256, 4)
mlp1_kernel(const float* __restrict__ W1, const float* __restrict__ b1) {
    mlp_body<true>(W1, b1, g_h, g_h);
}

__global__ void __launch_bounds__(256, 4)
mlp2_kernel(const float* __restrict__ W2, const float* __restrict__ b2) {
    mlp_body<false>(W2, b2, g_h, g_xres);
}

// ---------------------------------------------------------------------------
// Kernel 3: pocket pooling, atomic-free. Block = (graph b, slice s).
// ---------------------------------------------------------------------------
__global__ void pool_kernel(const float* __restrict__ mask) {
    __shared__ float sacc[8][KK * DD];
    __shared__ float scnt[8][KK];
    const int b = blockIdx.x / PS;
    const int s = blockIdx.x % PS;
    const int gs = g_gstart[b];
    const int len = g_gstart[b + 1] - gs;
    const int start = gs + (len * s) / PS;
    const int end = gs + (len * (s + 1)) / PS;

    const int wib = threadIdx.x >> 5;
    const int lane = threadIdx.x & 31;
    float* acc = sacc[wib];
    for (int i = lane; i < KK * DD; i += 32) acc[i] = 0.f;
    float cnt = 0.f;

    for (int n = start + wib; n < end; n += 8) {
        float m = (lane < KK) ? mask[(size_t)n * KK + lane] : 0.f;
        float4 xv = *(const float4*)(g_xres + (size_t)n * DD + lane * 4);
#pragma unroll
        for (int k = 0; k < KK; k++) {
            float mk = __shfl_sync(0xffffffffu, m, k);
            if (mk != 0.f) {
                float4* a = (float4*)(acc + k * DD + lane * 4);
                float4 v = *a;
                v.x += xv.x; v.y += xv.y; v.z += xv.z; v.w += xv.w;
                *a = v;
            }
        }
        cnt += m;
    }
    if (lane < KK) scnt[wib][lane] = cnt;
    __syncthreads();

    float* outp = g_part + (size_t)blockIdx.x * KK * DD;
    for (int i = threadIdx.x; i < KK * DD; i += blockDim.x) {
        float v = 0.f;
#pragma unroll
        for (int w = 0; w < 8; w++) v += sacc[w][i];
        outp[i] = v;
    }
    if (threadIdx.x < KK) {
        float c = 0.f;
#pragma unroll
        for (int w = 0; w < 8; w++) c += scnt[w][threadIdx.x];
        g_cntpart[blockIdx.x * KK + threadIdx.x] = c;
    }
}

// ---------------------------------------------------------------------------
// Kernel 3b: reduce partials -> g_psum, g_pcnt
// ---------------------------------------------------------------------------
__global__ void reduce_kernel() {
    int tid = blockIdx.x * blockDim.x + threadIdx.x;
    int stride = gridDim.x * blockDim.x;
    for (int i = tid; i < BB * KK * DD; i += stride) {
        int b = i / (KK * DD);
        int j = i % (KK * DD);
        float v = 0.f;
#pragma unroll
        for (int s = 0; s < PS; s++) v += g_part[(size_t)(b * PS + s) * KK * DD + j];
        g_psum[i] = v;
    }
    for (int i = tid; i < BB * KK; i += stride) {
        int b = i / KK;
        int k = i % KK;
        float c = 0.f;
#pragma unroll
        for (int s = 0; s < PS; s++) c += g_cntpart[(b * PS + s) * KK + k];
        g_pcnt[i] = c;
    }
}

// ---------------------------------------------------------------------------
// Kernel 4: pocket_emb = (psum/(cnt+1e-9)) @ Wv + bv. Warp per row (512 rows).
// ---------------------------------------------------------------------------
__global__ void pemb_kernel(const float* __restrict__ Wv, const float* __restrict__ bv) {
    const int lane = threadIdx.x & 31;
    const int r = blockIdx.x * (blockDim.x >> 5) + (threadIdx.x >> 5);
    if (r >= BB * KK) return;
    const float rinv = 1.f / (g_pcnt[r] + 1e-9f);
    const int c0 = lane * 4;
    float4 acc = *(const float4*)(bv + c0);
#pragma unroll 8
    for (int d = 0; d < DD; d++) {
        float a = g_psum[r * DD + d] * rinv;
        float4 w = __ldg((const float4*)(Wv + d * DD + c0));
        acc.x += a * w.x; acc.y += a * w.y; acc.z += a * w.z; acc.w += a * w.w;
    }
    *(float4*)(g_pemb + r * DD + c0) = acc;
}

// ---------------------------------------------------------------------------
// Kernel 5: residual pocket feedback + LayerNorm + ReLU. Warp per node.
// ---------------------------------------------------------------------------
__global__ void final_kernel(const float* __restrict__ mask, const int* __restrict__ batch,
                             const float* __restrict__ gamma, const float* __restrict__ beta,
                             float* __restrict__ out) {
    const int lane = threadIdx.x & 31;
    const int gw = blockIdx.x * (blockDim.x >> 5) + (threadIdx.x >> 5);
    const int tw = gridDim.x * (blockDim.x >> 5);
    const int c0 = lane * 4;
    const float4 gm = *(const float4*)(gamma + c0);
    const float4 bt = *(const float4*)(beta + c0);

    for (int n = gw; n < NN; n += tw) {
        int g = batch[n];
        float m = (lane < KK) ? mask[(size_t)n * KK + lane] : 0.f;
        float4 v = *(const float4*)(g_xres + (size_t)n * DD + c0);
        const float* pe = g_pemb + (size_t)g * KK * DD;
#pragma unroll
        for (int k = 0; k < KK; k++) {
            float mk = __shfl_sync(0xffffffffu, m, k);
            if (mk != 0.f) {
                float4 p = __ldg((const float4*)(pe + k * DD + c0));
                v.x += p.x; v.y += p.y; v.z += p.z; v.w += p.w;
            }
        }
        float s = v.x + v.y + v.z + v.w;
#pragma unroll
        for (int off = 16; off; off >>= 1) s += __shfl_xor_sync(0xffffffffu, s, off);
        float mu = s * (1.f / 128.f);
        float dx = v.x - mu, dy = v.y - mu, dz = v.z - mu, dw = v.w - mu;
        float sq = dx * dx + dy * dy + dz * dz + dw * dw;
#pragma unroll
        for (int off = 16; off; off >>= 1) sq += __shfl_xor_sync(0xffffffffu, sq, off);
        float rstd = rsqrtf(sq * (1.f / 128.f) + 1e-5f);
        float4 y;
        y.x = fmaxf(dx * rstd * gm.x + bt.x, 0.f);
        y.y = fmaxf(dy * rstd * gm.y + bt.y, 0.f);
        y.z = fmaxf(dz * rstd * gm.z + bt.z, 0.f);
        y.w = fmaxf(dw * rstd * gm.w + bt.w, 0.f);
        *(float4*)(out + (size_t)n * DD + c0) = y;
    }
}

// ---------------------------------------------------------------------------
extern "C" void kernel_launch(void* const* d_in, const int* in_sizes, int n_in,
                              void* d_out, int out_size) {
    const float* x     = (const float*)d_in[0];
    const int*   ei    = (const int*)d_in[1];
    const float* ea    = (const float*)d_in[2];
    const float* pmask = (const float*)d_in[3];
    const int*   batch = (const int*)d_in[4];
    const float* We    = (const float*)d_in[5];
    const float* be    = (const float*)d_in[6];
    const float* W1    = (const float*)d_in[7];
    const float* b1    = (const float*)d_in[8];
    const float* W2    = (const float*)d_in[9];
    const float* b2    = (const float*)d_in[10];
    const float* eps   = (const float*)d_in[11];
    const float* gamma = (const float*)d_in[12];
    const float* beta  = (const float*)d_in[13];
    const float* Wv    = (const float*)d_in[14];
    const float* bv    = (const float*)d_in[15];
    float* out = (float*)d_out;

    const int MLP_SMEM = (4096 + TM * DD) * 4;   // 49152 bytes (16KB Wq + 32KB A)
    cudaFuncSetAttribute(mlp1_kernel, cudaFuncAttributeMaxDynamicSharedMemorySize, MLP_SMEM);
    cudaFuncSetAttribute(mlp2_kernel, cudaFuncAttributeMaxDynamicSharedMemorySize, MLP_SMEM);

    init_kernel<<<2048, 256>>>(x, eps);
    bounds_kernel<<<(NN + 255) / 256, 256>>>(batch);
    edge_kernel<<<4096, 256>>>(x, ei, ea, We, be);
    mlp1_kernel<<<(NN + TM - 1) / TM, 256, MLP_SMEM>>>(W1, b1);
    mlp2_kernel<<<(NN + TM - 1) / TM, 256, MLP_SMEM>>>(W2, b2);
    pool_kernel<<<BB * PS, 256>>>(pmask);
    reduce_kernel<<<64, 256>>>();
    pemb_kernel<<<(BB * KK + 7) / 8, 256>>>(Wv, bv);
    final_kernel<<<2048, 256>>>(pmask, batch, gamma, beta, out);
}

// round 11
// speedup vs baseline: 1.8250x; 1.0844x over previous
#include <cuda_runtime.h>
#include <cuda_bf16.h>
#include <cstdint>

#define NN 50000
#define EE 600000
#define DD 128
#define KK 8
#define BB 64
#define ED 16
#define PS 8    // slices per graph for pooling
#define PADW 132 // padded row stride (floats) for conflict-free mma frag loads

// Scratch (device globals; no runtime alloc)
__device__ float g_h[NN * DD];            // (1+eps)*x + agg
__device__ float g_xres[NN * DD];         // MLP output
__device__ float g_psum[BB * KK * DD];    // pocket sums
__device__ float g_pcnt[BB * KK];         // pocket counts
__device__ float g_pemb[BB * KK * DD];    // pocket embeddings
__device__ int   g_gstart[BB + 1];        // graph start offsets (batch sorted)
__device__ float g_part[BB * PS * KK * DD];   // pooling partials (atomic-free)
__device__ float g_cntpart[BB * PS * KK];

// packed-fp32 helpers (FFMA2: exact fp32 math, 2x fma-pipe throughput)
#define FMA2(acc, a2, w2) \
    asm("fma.rn.f32x2 %0, %1, %2, %0;" : "+l"(acc) : "l"(a2), "l"(w2))
#define DUP2(a2, f) \
    asm("mov.b64 %0, {%1, %1};" : "=l"(a2) : "f"(f))
#define PACK2(p, lo, hi) \
    asm("mov.b64 %0, {%1, %2};" : "=l"(p) : "f"(lo), "f"(hi))
#define UNPACK2(lo, hi, p) \
    asm("mov.b64 {%0, %1}, %2;" : "=f"(lo), "=f"(hi) : "l"(p))

// tf32 helpers
__device__ __forceinline__ uint32_t tf32_hi(float f) {
    uint32_t u;
    asm("cvt.rna.tf32.f32 %0, %1;" : "=r"(u) : "f"(f));
    return u;
}
#define MMA_TF32(d, a0, a1, a2, a3, b0, b1) \
    asm volatile("mma.sync.aligned.m16n8k8.row.col.f32.tf32.tf32.f32 " \
                 "{%0,%1,%2,%3}, {%4,%5,%6,%7}, {%8,%9}, {%0,%1,%2,%3};" \
                 : "+f"(d[0]), "+f"(d[1]), "+f"(d[2]), "+f"(d[3]) \
                 : "r"(a0), "r"(a1), "r"(a2), "r"(a3), "r"(b0), "r"(b1))

// ---------------------------------------------------------------------------
// Kernel 0: g_h = (1+eps)*x
// ---------------------------------------------------------------------------
__global__ void init_kernel(const float* __restrict__ x, const float* __restrict__ epsp) {
    const float c = 1.0f + epsp[0];
    int tid = blockIdx.x * blockDim.x + threadIdx.x;
    int stride = gridDim.x * blockDim.x;
    const float4* x4 = (const float4*)x;
    float4* h4 = (float4*)g_h;
    for (int i = tid; i < NN * DD / 4; i += stride) {
        float4 v = x4[i];
        v.x *= c; v.y *= c; v.z *= c; v.w *= c;
        h4[i] = v;
    }
}

// ---------------------------------------------------------------------------
// Kernel 0b: graph boundary offsets from sorted batch
// ---------------------------------------------------------------------------
__global__ void bounds_kernel(const int* __restrict__ batch) {
    int n = blockIdx.x * blockDim.x + threadIdx.x;
    if (n >= NN) return;
    int b1 = batch[n];
    int b0 = (n == 0) ? -1 : batch[n - 1];
    for (int g = b0 + 1; g <= b1; g++) g_gstart[g] = n;
    if (n == NN - 1)
        for (int g = b1 + 1; g <= BB; g++) g_gstart[g] = NN;
}

// ---------------------------------------------------------------------------
// Kernel 1: edges. Warp processes 4 edges per iteration (R9 winner, unchanged)
// ---------------------------------------------------------------------------
__global__ void __launch_bounds__(256)
edge_kernel(const float* __restrict__ x,
            const int* __restrict__ ei,
            const float* __restrict__ ea,
            const float* __restrict__ We,
            const float* __restrict__ be) {
    __shared__ float sWe[ED * DD];
    __shared__ float sbe[DD];
    for (int i = threadIdx.x; i < ED * DD / 4; i += blockDim.x)
        ((float4*)sWe)[i] = ((const float4*)We)[i];
    if (threadIdx.x < DD) sbe[threadIdx.x] = be[threadIdx.x];
    __syncthreads();

    const int lane = threadIdx.x & 31;
    const int warp = blockIdx.x * (blockDim.x >> 5) + (threadIdx.x >> 5);
    const int nwarps = gridDim.x * (blockDim.x >> 5);
    const int* __restrict__ srcp = ei;
    const int* __restrict__ dstp = ei + EE;
    const int c0 = lane * 4;

    float4 bbv = *(const float4*)(&sbe[c0]);
    unsigned long long bp0, bp1;
    PACK2(bp0, bbv.x, bbv.y);
    PACK2(bp1, bbv.z, bbv.w);

    const int NG = EE / 4;
    for (int g = warp; g < NG; g += nwarps) {
        const int e0 = g * 4;
        const float* eab = ea + (size_t)e0 * ED;
        float r0 = __ldg(eab + lane);
        float r1 = __ldg(eab + lane + 32);
        int s0 = __ldg(srcp + e0 + 0), s1 = __ldg(srcp + e0 + 1);
        int s2 = __ldg(srcp + e0 + 2), s3 = __ldg(srcp + e0 + 3);
        int d0 = __ldg(dstp + e0 + 0), d1 = __ldg(dstp + e0 + 1);
        int d2 = __ldg(dstp + e0 + 2), d3 = __ldg(dstp + e0 + 3);

        unsigned long long acc[4][2];
#pragma unroll
        for (int i = 0; i < 4; i++) { acc[i][0] = bp0; acc[i][1] = bp1; }

#pragma unroll
        for (int j = 0; j < ED; j++) {
            ulonglong2 w = *(const ulonglong2*)(&sWe[j * DD + c0]);
            float a0 = __shfl_sync(0xffffffffu, r0, j);
            float a1 = __shfl_sync(0xffffffffu, r0, 16 + j);
            float a2 = __shfl_sync(0xffffffffu, r1, j);
            float a3 = __shfl_sync(0xffffffffu, r1, 16 + j);
            unsigned long long t0, t1, t2, t3;
            DUP2(t0, a0); FMA2(acc[0][0], t0, w.x); FMA2(acc[0][1], t0, w.y);
            DUP2(t1, a1); FMA2(acc[1][0], t1, w.x); FMA2(acc[1][1], t1, w.y);
            DUP2(t2, a2); FMA2(acc[2][0], t2, w.x); FMA2(acc[2][1], t2, w.y);
            DUP2(t3, a3); FMA2(acc[3][0], t3, w.x); FMA2(acc[3][1], t3, w.y);
        }

        const int sidx[4] = {s0, s1, s2, s3};
        const int didx[4] = {d0, d1, d2, d3};
#pragma unroll
        for (int i = 0; i < 4; i++) {
            float ex, ey, ez, ew;
            UNPACK2(ex, ey, acc[i][0]);
            UNPACK2(ez, ew, acc[i][1]);
            float4 xv = __ldg((const float4*)(x + (size_t)sidx[i] * DD + c0));
            float mx = fmaxf(ex + xv.x, 0.f);
            float my = fmaxf(ey + xv.y, 0.f);
            float mz = fmaxf(ez + xv.z, 0.f);
            float mw = fmaxf(ew + xv.w, 0.f);
            float* p = g_h + (size_t)didx[i] * DD + c0;
            asm volatile("red.global.add.v4.f32 [%0], {%1, %2, %3, %4};"
                         :: "l"(p), "f"(mx), "f"(my), "f"(mz), "f"(mw) : "memory");
        }
    }
}

// ---------------------------------------------------------------------------
// Kernel 2: FUSED node MLP on tensor cores (mma.sync m16n8k8 tf32, 3xTF32).
// Block = 64 rows; 8 warps, each owns a 16-col slice of the 128 outputs.
// W staged in 32-k-row quarters. GEMM1 result (relu) written back to sA,
// then GEMM2 -> g_xres. acc error ~2^-21 (3-term tf32 split).
// ---------------------------------------------------------------------------
__device__ __forceinline__ void mma_gemm_pass(const float* __restrict__ W,
                                              float* __restrict__ sW,
                                              const float* __restrict__ sA,
                                              float acc[4][2][4],
                                              int tq, int tr, int wcol, int tid) {
#pragma unroll 1
    for (int q = 0; q < 4; q++) {
        __syncthreads();
        for (int i = tid; i < 32 * 32; i += 256) {
            int r = i >> 5, c4 = i & 31;
            *(float4*)(sW + r * PADW + c4 * 4) =
                ((const float4*)(W + (size_t)(q * 32 + r) * DD))[c4];
        }
        __syncthreads();

#pragma unroll
        for (int ks = 0; ks < 4; ks++) {
            const int k0 = ks * 8;
            // B fragments (weights), hi+lo, 2 n-tiles
            uint32_t bh[2][2], bl[2][2];
#pragma unroll
            for (int ni = 0; ni < 2; ni++) {
                int col = wcol + ni * 8 + tq;
                float w0 = sW[(k0 + tr) * PADW + col];
                float w1 = sW[(k0 + tr + 4) * PADW + col];
                bh[ni][0] = tf32_hi(w0);
                bl[ni][0] = tf32_hi(w0 - __uint_as_float(bh[ni][0]));
                bh[ni][1] = tf32_hi(w1);
                bl[ni][1] = tf32_hi(w1 - __uint_as_float(bh[ni][1]));
            }
            const int kg = q * 32 + k0;
#pragma unroll
            for (int mi = 0; mi < 4; mi++) {
                const float* ap = sA + (mi * 16 + tq) * PADW + kg + tr;
                float a0 = ap[0];
                float a1 = ap[8 * PADW];
                float a2 = ap[4];
                float a3 = ap[8 * PADW + 4];
                uint32_t ah0 = tf32_hi(a0), ah1 = tf32_hi(a1);
                uint32_t ah2 = tf32_hi(a2), ah3 = tf32_hi(a3);
                uint32_t al0 = tf32_hi(a0 - __uint_as_float(ah0));
                uint32_t al1 = tf32_hi(a1 - __uint_as_float(ah1));
                uint32_t al2 = tf32_hi(a2 - __uint_as_float(ah2));
                uint32_t al3 = tf32_hi(a3 - __uint_as_float(ah3));
#pragma unroll
                for (int ni = 0; ni < 2; ni++) {
                    MMA_TF32(acc[mi][ni], ah0, ah1, ah2, ah3, bh[ni][0], bh[ni][1]);
                    MMA_TF32(acc[mi][ni], ah0, ah1, ah2, ah3, bl[ni][0], bl[ni][1]);
                    MMA_TF32(acc[mi][ni], al0, al1, al2, al3, bh[ni][0], bh[ni][1]);
                }
            }
        }
    }
}

__global__ void __launch_bounds__(256, 4)
mlp_fused_kernel(const float* __restrict__ W1, const float* __restrict__ b1,
                 const float* __restrict__ W2, const float* __restrict__ b2) {
    extern __shared__ float sm[];
    float* sW = sm;                  // 32 x PADW
    float* sA = sm + 32 * PADW;      // 64 x PADW
    const int tid = threadIdx.x;
    const int row0 = blockIdx.x * 64;

    // load A tile (fp32) into padded smem
    for (int i = tid; i < 64 * 32; i += 256) {
        int r = i >> 5, c4 = i & 31;
        float4 v = make_float4(0.f, 0.f, 0.f, 0.f);
        if (row0 + r < NN) v = ((const float4*)(g_h + (size_t)(row0 + r) * DD))[c4];
        *(float4*)(sA + r * PADW + c4 * 4) = v;
    }

    const int warp = tid >> 5, lane = tid & 31;
    const int tq = lane >> 2;   // lane/4: row-within-tile / col-within-ntile
    const int tr = lane & 3;    // lane%4: k index / col-pair index
    const int wcol = warp * 16;

    float acc[4][2][4];
#pragma unroll
    for (int mi = 0; mi < 4; mi++)
#pragma unroll
        for (int ni = 0; ni < 2; ni++)
#pragma unroll
            for (int v = 0; v < 4; v++) acc[mi][ni][v] = 0.f;

    // ---- GEMM1 ----
    mma_gemm_pass(W1, sW, sA, acc, tq, tr, wcol, tid);
    __syncthreads();   // all warps done reading sA before epilogue overwrites it

    // epilogue 1: relu(acc + b1) -> sA
    {
        float bias[2][2];
#pragma unroll
        for (int ni = 0; ni < 2; ni++) {
            bias[ni][0] = __ldg(b1 + wcol + ni * 8 + 2 * tr);
            bias[ni][1] = __ldg(b1 + wcol + ni * 8 + 2 * tr + 1);
        }
#pragma unroll
        for (int mi = 0; mi < 4; mi++) {
#pragma unroll
            for (int ni = 0; ni < 2; ni++) {
                int col = wcol + ni * 8 + 2 * tr;
                int r = mi * 16 + tq;
                float2 v0;
                v0.x = fmaxf(acc[mi][ni][0] + bias[ni][0], 0.f);
                v0.y = fmaxf(acc[mi][ni][1] + bias[ni][1], 0.f);
                *(float2*)(sA + r * PADW + col) = v0;
                float2 v1;
                v1.x = fmaxf(acc[mi][ni][2] + bias[ni][0], 0.f);
                v1.y = fmaxf(acc[mi][ni][3] + bias[ni][1], 0.f);
                *(float2*)(sA + (r + 8) * PADW + col) = v1;
                acc[mi][ni][0] = 0.f; acc[mi][ni][1] = 0.f;
                acc[mi][ni][2] = 0.f; acc[mi][ni][3] = 0.f;
            }
        }
    }
    __syncthreads();   // epilogue writes visible before GEMM2 reads sA

    // ---- GEMM2 ----
    mma_gemm_pass(W2, sW, sA, acc, tq, tr, wcol, tid);

    // epilogue 2: acc + b2 -> g_xres
    {
        float bias[2][2];
#pragma unroll
        for (int ni = 0; ni < 2; ni++) {
            bias[ni][0] = __ldg(b2 + wcol + ni * 8 + 2 * tr);
            bias[ni][1] = __ldg(b2 + wcol + ni * 8 + 2 * tr + 1);
        }
#pragma unroll
        for (int mi = 0; mi < 4; mi++) {
#pragma unroll
            for (int ni = 0; ni < 2; ni++) {
                int col = wcol + ni * 8 + 2 * tr;
                int r = row0 + mi * 16 + tq;
                if (r < NN) {
                    float2 v;
                    v.x = acc[mi][ni][0] + bias[ni][0];
                    v.y = acc[mi][ni][1] + bias[ni][1];
                    *(float2*)(g_xres + (size_t)r * DD + col) = v;
                }
                if (r + 8 < NN) {
                    float2 v;
                    v.x = acc[mi][ni][2] + bias[ni][0];
                    v.y = acc[mi][ni][3] + bias[ni][1];
                    *(float2*)(g_xres + (size_t)(r + 8) * DD + col) = v;
                }
            }
        }
    }
}

// ---------------------------------------------------------------------------
// Kernel 3: pocket pooling, atomic-free. Block = (graph b, slice s).
// ---------------------------------------------------------------------------
__global__ void pool_kernel(const float* __restrict__ mask) {
    __shared__ float sacc[8][KK * DD];
    __shared__ float scnt[8][KK];
    const int b = blockIdx.x / PS;
    const int s = blockIdx.x % PS;
    const int gs = g_gstart[b];
    const int len = g_gstart[b + 1] - gs;
    const int start = gs + (len * s) / PS;
    const int end = gs + (len * (s + 1)) / PS;

    const int wib = threadIdx.x >> 5;
    const int lane = threadIdx.x & 31;
    float* acc = sacc[wib];
    for (int i = lane; i < KK * DD; i += 32) acc[i] = 0.f;
    float cnt = 0.f;

    for (int n = start + wib; n < end; n += 8) {
        float m = (lane < KK) ? mask[(size_t)n * KK + lane] : 0.f;
        float4 xv = *(const float4*)(g_xres + (size_t)n * DD + lane * 4);
#pragma unroll
        for (int k = 0; k < KK; k++) {
            float mk = __shfl_sync(0xffffffffu, m, k);
            if (mk != 0.f) {
                float4* a = (float4*)(acc + k * DD + lane * 4);
                float4 v = *a;
                v.x += xv.x; v.y += xv.y; v.z += xv.z; v.w += xv.w;
                *a = v;
            }
        }
        cnt += m;
    }
    if (lane < KK) scnt[wib][lane] = cnt;
    __syncthreads();

    float* outp = g_part + (size_t)blockIdx.x * KK * DD;
    for (int i = threadIdx.x; i < KK * DD; i += blockDim.x) {
        float v = 0.f;
#pragma unroll
        for (int w = 0; w < 8; w++) v += sacc[w][i];
        outp[i] = v;
    }
    if (threadIdx.x < KK) {
        float c = 0.f;
#pragma unroll
        for (int w = 0; w < 8; w++) c += scnt[w][threadIdx.x];
        g_cntpart[blockIdx.x * KK + threadIdx.x] = c;
    }
}

// ---------------------------------------------------------------------------
// Kernel 3b: reduce partials -> g_psum, g_pcnt
// ---------------------------------------------------------------------------
__global__ void reduce_kernel() {
    int tid = blockIdx.x * blockDim.x + threadIdx.x;
    int stride = gridDim.x * blockDim.x;
    for (int i = tid; i < BB * KK * DD; i += stride) {
        int b = i / (KK * DD);
        int j = i % (KK * DD);
        float v = 0.f;
#pragma unroll
        for (int s = 0; s < PS; s++) v += g_part[(size_t)(b * PS + s) * KK * DD + j];
        g_psum[i] = v;
    }
    for (int i = tid; i < BB * KK; i += stride) {
        int b = i / KK;
        int k = i % KK;
        float c = 0.f;
#pragma unroll
        for (int s = 0; s < PS; s++) c += g_cntpart[(b * PS + s) * KK + k];
        g_pcnt[i] = c;
    }
}

// ---------------------------------------------------------------------------
// Kernel 4: pocket_emb = (psum/(cnt+1e-9)) @ Wv + bv. Warp per row (512 rows).
// ---------------------------------------------------------------------------
__global__ void pemb_kernel(const float* __restrict__ Wv, const float* __restrict__ bv) {
    const int lane = threadIdx.x & 31;
    const int r = blockIdx.x * (blockDim.x >> 5) + (threadIdx.x >> 5);
    if (r >= BB * KK) return;
    const float rinv = 1.f / (g_pcnt[r] + 1e-9f);
    const int c0 = lane * 4;
    float4 acc = *(const float4*)(bv + c0);
#pragma unroll 8
    for (int d = 0; d < DD; d++) {
        float a = g_psum[r * DD + d] * rinv;
        float4 w = __ldg((const float4*)(Wv + d * DD + c0));
        acc.x += a * w.x; acc.y += a * w.y; acc.z += a * w.z; acc.w += a * w.w;
    }
    *(float4*)(g_pemb + r * DD + c0) = acc;
}

// ---------------------------------------------------------------------------
// Kernel 5: residual pocket feedback + LayerNorm + ReLU. Warp per node.
// ---------------------------------------------------------------------------
__global__ void final_kernel(const float* __restrict__ mask, const int* __restrict__ batch,
                             const float* __restrict__ gamma, const float* __restrict__ beta,
                             float* __restrict__ out) {
    const int lane = threadIdx.x & 31;
    const int gw = blockIdx.x * (blockDim.x >> 5) + (threadIdx.x >> 5);
    const int tw = gridDim.x * (blockDim.x >> 5);
    const int c0 = lane * 4;
    const float4 gm = *(const float4*)(gamma + c0);
    const float4 bt = *(const float4*)(beta + c0);

    for (int n = gw; n < NN; n += tw) {
        int g = batch[n];
        float m = (lane < KK) ? mask[(size_t)n * KK + lane] : 0.f;
        float4 v = *(const float4*)(g_xres + (size_t)n * DD + c0);
        const float* pe = g_pemb + (size_t)g * KK * DD;
#pragma unroll
        for (int k = 0; k < KK; k++) {
            float mk = __shfl_sync(0xffffffffu, m, k);
            if (mk != 0.f) {
                float4 p = __ldg((const float4*)(pe + k * DD + c0));
                v.x += p.x; v.y += p.y; v.z += p.z; v.w += p.w;
            }
        }
        float s = v.x + v.y + v.z + v.w;
#pragma unroll
        for (int off = 16; off; off >>= 1) s += __shfl_xor_sync(0xffffffffu, s, off);
        float mu = s * (1.f / 128.f);
        float dx = v.x - mu, dy = v.y - mu, dz = v.z - mu, dw = v.w - mu;
        float sq = dx * dx + dy * dy + dz * dz + dw * dw;
#pragma unroll
        for (int off = 16; off; off >>= 1) sq += __shfl_xor_sync(0xffffffffu, sq, off);
        float rstd = rsqrtf(sq * (1.f / 128.f) + 1e-5f);
        float4 y;
        y.x = fmaxf(dx * rstd * gm.x + bt.x, 0.f);
        y.y = fmaxf(dy * rstd * gm.y + bt.y, 0.f);
        y.z = fmaxf(dz * rstd * gm.z + bt.z, 0.f);
        y.w = fmaxf(dw * rstd * gm.w + bt.w, 0.f);
        *(float4*)(out + (size_t)n * DD + c0) = y;
    }
}

// ---------------------------------------------------------------------------
extern "C" void kernel_launch(void* const* d_in, const int* in_sizes, int n_in,
                              void* d_out, int out_size) {
    const float* x     = (const float*)d_in[0];
    const int*   ei    = (const int*)d_in[1];
    const float* ea    = (const float*)d_in[2];
    const float* pmask = (const float*)d_in[3];
    const int*   batch = (const int*)d_in[4];
    const float* We    = (const float*)d_in[5];
    const float* be    = (const float*)d_in[6];
    const float* W1    = (const float*)d_in[7];
    const float* b1    = (const float*)d_in[8];
    const float* W2    = (const float*)d_in[9];
    const float* b2    = (const float*)d_in[10];
    const float* eps   = (const float*)d_in[11];
    const float* gamma = (const float*)d_in[12];
    const float* beta  = (const float*)d_in[13];
    const float* Wv    = (const float*)d_in[14];
    const float* bv    = (const float*)d_in[15];
    float* out = (float*)d_out;

    const int MLP_SMEM = (32 + 64) * PADW * 4;   // 50688 bytes
    cudaFuncSetAttribute(mlp_fused_kernel, cudaFuncAttributeMaxDynamicSharedMemorySize, MLP_SMEM);

    init_kernel<<<2048, 256>>>(x, eps);
    bounds_kernel<<<(NN + 255) / 256, 256>>>(batch);
    edge_kernel<<<4096, 256>>>(x, ei, ea, We, be);
    mlp_fused_kernel<<<(NN + 63) / 64, 256, MLP_SMEM>>>(W1, b1, W2, b2);
    pool_kernel<<<BB * PS, 256>>>(pmask);
    reduce_kernel<<<64, 256>>>();
    pemb_kernel<<<(BB * KK + 7) / 8, 256>>>(Wv, bv);
    final_kernel<<<2048, 256>>>(pmask, batch, gamma, beta, out);
}